// round 14
// baseline (speedup 1.0000x reference)
#include <cuda_runtime.h>
#include <cuda_bf16.h>
#include <mma.h>
#include <cstdlib>

using namespace nvcuda;

// Problem constants (fixed by setup_inputs)
#define BATCH   2
#define HH      128
#define WW      128
#define N_PIX   16384          // HH*WW
#define CC      256
#define NHEADS  8
#define HD      32             // CC / NHEADS
#define GG      16             // BATCH * NHEADS
#define KPTS    9
#define MTOT    32768          // BATCH * N_PIX

// ---- force EAGER module loading BEFORE any CUDA call anywhere ----
// (validated passing config — do not touch)
__attribute__((constructor))
static void hx_force_eager_module_loading() {
    setenv("CUDA_MODULE_LOADING", "EAGER", 1);
}

// -------- single scratch segment: exactly 128 MiB --------
// q  : [0,         8388608)   (g, n, d)           floats
// kv : [8388608,  25165824)   (g, n, d) float2 {k,v} interleaved
// ao : [25165824, 33554432)   (b, n, c)           floats
#define OFF_Q   0u
#define OFF_KV  8388608u
#define OFF_AO  25165824u
#define SCRATCH_FLOATS 33554432u

__device__ __align__(16) float g_scratch[SCRATCH_FLOATS];

// ======================= tf32 tensor-core GEMM =======================
// C[m][o] = sum_c A[m][c] * B[o][c]
// Block tile 128(m) x 64(n), BK=32, 8 warps in 4x2, warp tile 32x32 (2x2 wmma m16n16k8).
// MODE 0: A = x, scatter C into q / interleaved-kv slices     (Nout=768)
// MODE 1: A = g_scratch[ao], C = Co + bias                    (Nout=256)
#define AS_LD 40
#define BS_LD 40
#define CS_LD 68
#define AS_OFF 0
#define BS_OFF (128 * AS_LD)
#define SM_FLOATS (128 * CS_LD)

template<int MODE>
__global__ void __launch_bounds__(256)
k_gemm_tc(const float* __restrict__ Ain, const float* __restrict__ Bw,
          const float* __restrict__ bias, float* __restrict__ Co)
{
    const int K = 256;
    const float* A = (MODE == 0) ? Ain : &g_scratch[OFF_AO];

    __shared__ float sm[SM_FLOATS];

    const int tid = threadIdx.x;
    const int wid = tid >> 5;
    const int m0 = blockIdx.y * 128;
    const int n0 = blockIdx.x * 64;

    const int warp_m = wid >> 1;
    const int warp_n = wid & 1;
    const int row_a = warp_m * 32;
    const int col_b = warp_n * 32;

    wmma::fragment<wmma::accumulator, 16, 16, 8, float> cf[2][2];
    #pragma unroll
    for (int i = 0; i < 2; i++)
        #pragma unroll
        for (int j = 0; j < 2; j++)
            wmma::fill_fragment(cf[i][j], 0.0f);

    const int lrow = tid >> 3;
    const int lcol = (tid & 7) << 2;

    for (int k0 = 0; k0 < K; k0 += 32) {
        #pragma unroll
        for (int p = 0; p < 4; p++) {
            int r = p * 32 + lrow;
            float4 v = *(const float4*)(A + (size_t)(m0 + r) * K + k0 + lcol);
            float* d = &sm[AS_OFF + r * AS_LD + lcol];
            d[0] = v.x; d[1] = v.y; d[2] = v.z; d[3] = v.w;
        }
        #pragma unroll
        for (int p = 0; p < 2; p++) {
            int r = p * 32 + lrow;
            float4 v = *(const float4*)(Bw + (size_t)(n0 + r) * K + k0 + lcol);
            float* d = &sm[BS_OFF + r * BS_LD + lcol];
            d[0] = v.x; d[1] = v.y; d[2] = v.z; d[3] = v.w;
        }
        __syncthreads();

        #pragma unroll
        for (int kk = 0; kk < 4; kk++) {
            wmma::fragment<wmma::matrix_a, 16, 16, 8, wmma::precision::tf32, wmma::row_major> af[2];
            wmma::fragment<wmma::matrix_b, 16, 16, 8, wmma::precision::tf32, wmma::col_major> bf[2];
            const float* ap = &sm[AS_OFF + row_a * AS_LD + kk * 8];
            wmma::load_matrix_sync(af[0], ap, AS_LD);
            wmma::load_matrix_sync(af[1], ap + 16 * AS_LD, AS_LD);
            const float* bp = &sm[BS_OFF + col_b * BS_LD + kk * 8];
            wmma::load_matrix_sync(bf[0], bp, BS_LD);
            wmma::load_matrix_sync(bf[1], bp + 16 * BS_LD, BS_LD);

            #pragma unroll
            for (int i = 0; i < 2; i++)
                #pragma unroll
                for (int t = 0; t < af[i].num_elements; t++)
                    af[i].x[t] = wmma::__float_to_tf32(af[i].x[t]);
            #pragma unroll
            for (int j = 0; j < 2; j++)
                #pragma unroll
                for (int t = 0; t < bf[j].num_elements; t++)
                    bf[j].x[t] = wmma::__float_to_tf32(bf[j].x[t]);

            #pragma unroll
            for (int i = 0; i < 2; i++)
                #pragma unroll
                for (int j = 0; j < 2; j++)
                    wmma::mma_sync(cf[i][j], af[i], bf[j], cf[i][j]);
        }
        __syncthreads();
    }

    #pragma unroll
    for (int i = 0; i < 2; i++)
        #pragma unroll
        for (int j = 0; j < 2; j++)
            wmma::store_matrix_sync(&sm[(row_a + i * 16) * CS_LD + col_b + j * 16],
                                    cf[i][j], CS_LD, wmma::mem_row_major);
    __syncthreads();

    #pragma unroll
    for (int t = 0; t < 32; t++) {
        int idx = t * 256 + tid;
        int r = idx >> 6;
        int c = idx & 63;
        float val = sm[r * CS_LD + c];
        int m = m0 + r;
        int o = n0 + c;
        if (MODE == 0) {
            int b = m >> 14;
            int n = m & (N_PIX - 1);
            int which = o >> 8;              // 0=q,1=k,2=v
            int h = (o >> 5) & 7;
            int d = o & 31;
            int g = b * NHEADS + h;
            unsigned pidx = ((unsigned)g * N_PIX + n) * HD + d;
            if (which == 0) {
                g_scratch[OFF_Q + pidx] = val;
            } else {
                // interleaved kv: {k, v} float pairs
                g_scratch[OFF_KV + pidx * 2 + (which - 1)] = val;
            }
        } else {
            Co[(size_t)m * CC + o] = val + bias[o];
        }
    }
}

// ======================= deformable attention (offsets fused) ===============
// one warp per (g, n); lane = channel d
// gather phase (all 36 float2 corner loads) then one joint 9-way butterfly.
__global__ void __launch_bounds__(256)
k_attn(const float* __restrict__ x, const float* __restrict__ Woff)
{
    int warp = (blockIdx.x * blockDim.x + threadIdx.x) >> 5;
    int lane = threadIdx.x & 31;
    int n = warp & (N_PIX - 1);
    int g = warp >> 14;
    int b = g >> 3;
    int h = g & 7;

    float xv = x[((size_t)(b * N_PIX + n)) * CC + h * HD + lane];
    float qd = g_scratch[OFF_Q + ((unsigned)g * N_PIX + n) * HD + lane];

    // offset projection (transpose formulation): lane o<18 gets offs = x_head . Woff[o]
    float offs = 0.0f;
    #pragma unroll
    for (int d = 0; d < HD; d++) {
        float xd = __shfl_sync(0xFFFFFFFFu, xv, d);
        float wv = (lane < 2 * KPTS) ? __ldg(&Woff[lane * HD + d]) : 0.0f;
        offs = fmaf(xd, wv, offs);
    }

    int py = n >> 7;
    int px = n & (WW - 1);

    const float scale = 0.17677669529663687f;  // hd^-0.5
    const float2* kvbuf = (const float2*)&g_scratch[OFF_KV];
    const unsigned gbase = (unsigned)g * N_PIX;

    float pl[KPTS];   // per-lane partial logits
    float vsl[KPTS];  // per-lane sampled v

    // ---- gather phase: all loads issued, no cross-lane dependencies ----
    #pragma unroll
    for (int kp = 0; kp < KPTS; kp++) {
        float dy = __shfl_sync(0xFFFFFFFFu, offs, 2 * kp + 0);
        float dx = __shfl_sync(0xFFFFFFFFu, offs, 2 * kp + 1);

        float sy = (float)(py + kp / 3 - 1) + dy;
        float sx = (float)(px + kp % 3 - 1) + dx;

        float y0f = floorf(sy), x0f = floorf(sx);
        float wy1 = sy - y0f, wx1 = sx - x0f;
        float wy0 = 1.0f - wy1, wx0 = 1.0f - wx1;
        int y0 = (int)y0f, x0 = (int)x0f;

        float ka = 0.0f, va = 0.0f;
        #pragma unroll
        for (int c = 0; c < 4; c++) {
            int yy = y0 + (c >> 1);
            int xx = x0 + (c & 1);
            float w = ((c >> 1) ? wy1 : wy0) * ((c & 1) ? wx1 : wx0);
            if (yy >= 0 && yy < HH && xx >= 0 && xx < WW) {
                float2 kv = kvbuf[(gbase + (yy << 7) + xx) * HD + lane];
                ka = fmaf(w, kv.x, ka);
                va = fmaf(w, kv.y, va);
            }
        }
        pl[kp]  = qd * ka;
        vsl[kp] = va;
    }

    // ---- joint butterfly reduction: 9 independent chains per level ----
    #pragma unroll
    for (int s = 16; s > 0; s >>= 1) {
        #pragma unroll
        for (int kp = 0; kp < KPTS; kp++)
            pl[kp] += __shfl_xor_sync(0xFFFFFFFFu, pl[kp], s);
    }

    // softmax over 9 (replicated per lane; pl now full logits on every lane)
    float mx = pl[0] * scale;
    #pragma unroll
    for (int kp = 1; kp < KPTS; kp++) mx = fmaxf(mx, pl[kp] * scale);
    float se = 0.0f;
    float wgt[KPTS];
    #pragma unroll
    for (int kp = 0; kp < KPTS; kp++) { wgt[kp] = __expf(pl[kp] * scale - mx); se += wgt[kp]; }
    float inv = 1.0f / se;

    float od = 0.0f;
    #pragma unroll
    for (int kp = 0; kp < KPTS; kp++) od = fmaf(vsl[kp], wgt[kp], od);
    od *= inv;

    g_scratch[OFF_AO + ((unsigned)(b * N_PIX + n)) * CC + h * HD + lane] = od;
}

// ======================= launch =======================
extern "C" void kernel_launch(void* const* d_in, const int* in_sizes, int n_in,
                              void* d_out, int out_size)
{
    const float* x     = (const float*)d_in[0];
    const float* Wqkv  = (const float*)d_in[1];
    const float* Woff  = (const float*)d_in[2];
    const float* Wproj = (const float*)d_in[3];
    const float* bproj = (const float*)d_in[4];
    float* out = (float*)d_out;

    // 1) QKV projection (tf32 tensor cores): (32768,256)@(768,256)^T -> q/kv
    {
        dim3 grid(768 / 64, MTOT / 128);
        k_gemm_tc<0><<<grid, 256>>>(x, Wqkv, nullptr, nullptr);
    }
    // 2) deformable attention (offset projection fused in)
    {
        int warps = GG * N_PIX;
        k_attn<<<warps / 8, 256>>>(x, Woff);
    }
    // 3) output projection (tf32 tensor cores)
    {
        dim3 grid(CC / 64, MTOT / 128);
        k_gemm_tc<1><<<grid, 256>>>(nullptr, Wproj, bproj, out);
    }
}